// round 3
// baseline (speedup 1.0000x reference)
#include <cuda_runtime.h>
#include <cstdint>

#define T_HASH 524288      // 2^19 -> mod == & mask, low-32-bit arithmetic suffices
#define HMASK  (T_HASH - 1)
#define PI2    2654435761u
#define PI3    805459861u

// ---- packed f32x2 helpers (Blackwell FFMA2 is only reachable via PTX) ----
__device__ __forceinline__ unsigned long long pk2(float v) {
    unsigned long long r;
    asm("mov.b64 %0, {%1, %1};" : "=l"(r) : "f"(v));
    return r;
}
__device__ __forceinline__ unsigned long long fma2(unsigned long long a,
                                                   unsigned long long b,
                                                   unsigned long long c) {
    unsigned long long d;
    asm("fma.rn.f32x2 %0, %1, %2, %3;" : "=l"(d) : "l"(a), "l"(b), "l"(c));
    return d;
}
__device__ __forceinline__ void unpk(unsigned long long v, float& a, float& b) {
    asm("mov.b64 {%0, %1}, %2;" : "=f"(a), "=f"(b) : "l"(v));
}

// smem weight layout (float offsets)
#define OW1A 0       // [32,64]  2048
#define OB1A 2048    // [64]
#define OW1B 2112    // [64,16]  1024
#define OB1B 3136    // [16]
#define OW2A 3152    // [43,64]  2752
#define OB2A 5904    // [64]
#define OW2B 5968    // [64,64]  4096
#define OB2B 10064   // [64]
#define OW2C 10128   // [64,3]   192
#define OB2C 10320   // [3]
#define SWTOT 10324

__global__ __launch_bounds__(128, 2)
void ngp_fused_kernel(const float* __restrict__ x, const float* __restrict__ ddir,
                      const float* __restrict__ tables,
                      const float* __restrict__ w1a, const float* __restrict__ b1a,
                      const float* __restrict__ w1b, const float* __restrict__ b1b,
                      const float* __restrict__ w2a, const float* __restrict__ b2a,
                      const float* __restrict__ w2b, const float* __restrict__ b2b,
                      const float* __restrict__ w2c, const float* __restrict__ b2c,
                      float* __restrict__ out, int n)
{
    __shared__ __align__(16) float sw[SWTOT];

    // cooperative weight staging into smem
    {
        const float* srcs[10] = {w1a, b1a, w1b, b1b, w2a, b2a, w2b, b2b, w2c, b2c};
        const int offs[10]    = {OW1A, OB1A, OW1B, OB1B, OW2A, OB2A, OW2B, OB2B, OW2C, OB2C};
        const int lens[10]    = {2048, 64, 1024, 16, 2752, 64, 4096, 64, 192, 3};
        #pragma unroll
        for (int s = 0; s < 10; s++)
            for (int idx = threadIdx.x; idx < lens[s]; idx += blockDim.x)
                sw[offs[s] + idx] = srcs[s][idx];
    }
    __syncthreads();

    int i = blockIdx.x * blockDim.x + threadIdx.x;
    if (i >= n) return;

    float x0 = x[3 * i + 0], x1 = x[3 * i + 1], x2 = x[3 * i + 2];
    float d0 = ddir[3 * i + 0], d1 = ddir[3 * i + 1], d2 = ddir[3 * i + 2];

    float xs0 = __fdiv_rn(x0, 3.0f), xs1 = __fdiv_rn(x1, 3.0f), xs2 = __fdiv_rn(x2, 3.0f);
    bool mask = (fabsf(xs0) < 0.5f) && (fabsf(xs1) < 0.5f) && (fabsf(xs2) < 0.5f);
    float xu0 = xs0 + 0.5f, xu1 = xs1 + 0.5f, xu2 = xs2 + 0.5f;

    // ---------------- hash-grid feature gather ----------------
    const float NLv[16] = {16.f, 22.f, 30.f, 42.f, 58.f, 80.f, 110.f, 152.f,
                           209.f, 288.f, 397.f, 547.f, 754.f, 1039.f, 1432.f, 1974.f};
    float feats[32];
    const float2* tb2 = (const float2*)tables;

    #pragma unroll
    for (int l = 0; l < 16; l++) {
        float nl = NLv[l];
        float p0 = xu0 * nl, p1 = xu1 * nl, p2 = xu2 * nl;
        float f0 = floorf(p0), f1 = floorf(p1), f2 = floorf(p2);
        float r0 = p0 - f0, r1 = p1 - f1, r2 = p2 - f2;
        float a0 = 1.0f - r0, a1 = 1.0f - r1, a2 = 1.0f - r2;

        // int64 hash ≡ low-32-bit hash because T = 2^19 and % T picks low bits
        unsigned hx0 = (unsigned)(int)f0;                 // * 1
        unsigned hy0 = (unsigned)(int)f1 * PI2;
        unsigned hz0 = (unsigned)(int)f2 * PI3;
        unsigned hx1 = hx0 + (r0 > 0.0f ? 1u   : 0u);     // ceil variant
        unsigned hy1 = hy0 + (r1 > 0.0f ? PI2  : 0u);
        unsigned hz1 = hz0 + (r2 > 0.0f ? PI3  : 0u);

        const float2* tbl = tb2 + (size_t)l * T_HASH;
        float acc0 = 0.0f, acc1 = 0.0f;
        // CEIL bit masks per vertex k: x:{1,5,6,7}=0xE2 y:{2,4,6,7}=0xD4 z:{3,4,5,7}=0xB8
        #pragma unroll
        for (int k = 0; k < 8; k++) {
            unsigned hh = (((0xE2 >> k) & 1) ? hx1 : hx0)
                        ^ (((0xD4 >> k) & 1) ? hy1 : hy0)
                        ^ (((0xB8 >> k) & 1) ? hz1 : hz0);
            hh &= HMASK;
            // WEIGHT bits (grid_sample mismatch, faithful): x=k&1, y=k&2, z=k&4
            float w = ((k & 1) ? r0 : a0) * ((k & 2) ? r1 : a1) * ((k & 4) ? r2 : a2);
            float2 t = __ldg(tbl + hh);
            acc0 = fmaf(w, t.x, acc0);
            acc1 = fmaf(w, t.y, acc1);
        }
        feats[2 * l + 0] = acc0;
        feats[2 * l + 1] = acc1;
    }

    // ---------------- MLP layer 1a: 32 -> 64, relu ----------------
    unsigned long long acc[32];
    {
        const unsigned long long* pb = (const unsigned long long*)(sw + OB1A);
        #pragma unroll
        for (int j = 0; j < 32; j++) acc[j] = pb[j];
        #pragma unroll 4
        for (int k = 0; k < 32; k++) {
            unsigned long long bv = pk2(feats[k]);
            const ulonglong2* wr = (const ulonglong2*)(sw + OW1A + k * 64);
            #pragma unroll
            for (int j = 0; j < 16; j++) {
                ulonglong2 ww = wr[j];
                acc[2 * j + 0] = fma2(bv, ww.x, acc[2 * j + 0]);
                acc[2 * j + 1] = fma2(bv, ww.y, acc[2 * j + 1]);
            }
        }
    }
    float h1[64];
    #pragma unroll
    for (int j = 0; j < 32; j++) {
        float a, b;
        unpk(acc[j], a, b);
        h1[2 * j + 0] = fmaxf(a, 0.0f);
        h1[2 * j + 1] = fmaxf(b, 0.0f);
    }

    // ---------------- MLP layer 1b: 64 -> 16 (no relu) ----------------
    float hh16[16];
    {
        unsigned long long acc2[8];
        const unsigned long long* pb = (const unsigned long long*)(sw + OB1B);
        #pragma unroll
        for (int j = 0; j < 8; j++) acc2[j] = pb[j];
        #pragma unroll 8
        for (int k = 0; k < 64; k++) {
            unsigned long long bv = pk2(h1[k]);
            const ulonglong2* wr = (const ulonglong2*)(sw + OW1B + k * 16);
            #pragma unroll
            for (int j = 0; j < 4; j++) {
                ulonglong2 ww = wr[j];
                acc2[2 * j + 0] = fma2(bv, ww.x, acc2[2 * j + 0]);
                acc2[2 * j + 1] = fma2(bv, ww.y, acc2[2 * j + 1]);
            }
        }
        #pragma unroll
        for (int j = 0; j < 8; j++) unpk(acc2[j], hh16[2 * j], hh16[2 * j + 1]);
    }

    float sigma = mask ? __expf(hh16[0]) : 0.0f;

    // ---------------- z = [h(16), d(3), sin/cos posenc(24)] ----------------
    float z[43];
    #pragma unroll
    for (int j = 0; j < 16; j++) z[j] = hh16[j];
    z[16] = d0; z[17] = d1; z[18] = d2;
    #pragma unroll
    for (int q = 0; q < 4; q++) {
        float m = (float)(1 << q);
        float s, c;
        __sincosf(m * d0, &s, &c); z[19 + 6 * q + 0] = s; z[22 + 6 * q + 0] = c;
        __sincosf(m * d1, &s, &c); z[19 + 6 * q + 1] = s; z[22 + 6 * q + 1] = c;
        __sincosf(m * d2, &s, &c); z[19 + 6 * q + 2] = s; z[22 + 6 * q + 2] = c;
    }

    // ---------------- MLP layer 2a: 43 -> 64, relu ----------------
    {
        const unsigned long long* pb = (const unsigned long long*)(sw + OB2A);
        #pragma unroll
        for (int j = 0; j < 32; j++) acc[j] = pb[j];
        #pragma unroll 4
        for (int k = 0; k < 43; k++) {
            unsigned long long bv = pk2(z[k]);
            const ulonglong2* wr = (const ulonglong2*)(sw + OW2A + k * 64);
            #pragma unroll
            for (int j = 0; j < 16; j++) {
                ulonglong2 ww = wr[j];
                acc[2 * j + 0] = fma2(bv, ww.x, acc[2 * j + 0]);
                acc[2 * j + 1] = fma2(bv, ww.y, acc[2 * j + 1]);
            }
        }
        #pragma unroll
        for (int j = 0; j < 32; j++) {
            float a, b;
            unpk(acc[j], a, b);
            h1[2 * j + 0] = fmaxf(a, 0.0f);   // reuse h1 as za[64]
            h1[2 * j + 1] = fmaxf(b, 0.0f);
        }
    }

    // ---------------- MLP layer 2b: 64 -> 64, relu ----------------
    float zb[64];
    {
        const unsigned long long* pb = (const unsigned long long*)(sw + OB2B);
        #pragma unroll
        for (int j = 0; j < 32; j++) acc[j] = pb[j];
        #pragma unroll 4
        for (int k = 0; k < 64; k++) {
            unsigned long long bv = pk2(h1[k]);
            const ulonglong2* wr = (const ulonglong2*)(sw + OW2B + k * 64);
            #pragma unroll
            for (int j = 0; j < 16; j++) {
                ulonglong2 ww = wr[j];
                acc[2 * j + 0] = fma2(bv, ww.x, acc[2 * j + 0]);
                acc[2 * j + 1] = fma2(bv, ww.y, acc[2 * j + 1]);
            }
        }
        #pragma unroll
        for (int j = 0; j < 32; j++) {
            float a, b;
            unpk(acc[j], a, b);
            zb[2 * j + 0] = fmaxf(a, 0.0f);
            zb[2 * j + 1] = fmaxf(b, 0.0f);
        }
    }

    // ---------------- MLP layer 2c: 64 -> 3, sigmoid ----------------
    float c0 = sw[OB2C + 0], c1 = sw[OB2C + 1], c2 = sw[OB2C + 2];
    #pragma unroll 8
    for (int k = 0; k < 64; k++) {
        float v = zb[k];
        c0 = fmaf(v, sw[OW2C + 3 * k + 0], c0);
        c1 = fmaf(v, sw[OW2C + 3 * k + 1], c1);
        c2 = fmaf(v, sw[OW2C + 3 * k + 2], c2);
    }
    c0 = 1.0f / (1.0f + __expf(-c0));
    c1 = 1.0f / (1.0f + __expf(-c1));
    c2 = 1.0f / (1.0f + __expf(-c2));

    out[3 * i + 0] = mask ? c0 : 0.0f;
    out[3 * i + 1] = mask ? c1 : 0.0f;
    out[3 * i + 2] = mask ? c2 : 0.0f;
    out[3 * n + i] = sigma;
}

extern "C" void kernel_launch(void* const* d_in, const int* in_sizes, int n_in,
                              void* d_out, int out_size) {
    const float* x      = (const float*)d_in[0];
    const float* dd     = (const float*)d_in[1];
    const float* tables = (const float*)d_in[2];
    const float* w1a = (const float*)d_in[3];
    const float* b1a = (const float*)d_in[4];
    const float* w1b = (const float*)d_in[5];
    const float* b1b = (const float*)d_in[6];
    const float* w2a = (const float*)d_in[7];
    const float* b2a = (const float*)d_in[8];
    const float* w2b = (const float*)d_in[9];
    const float* b2b = (const float*)d_in[10];
    const float* w2c = (const float*)d_in[11];
    const float* b2c = (const float*)d_in[12];

    int n = in_sizes[0] / 3;
    int threads = 128;
    int blocks = (n + threads - 1) / threads;
    ngp_fused_kernel<<<blocks, threads>>>(x, dd, tables,
                                          w1a, b1a, w1b, b1b,
                                          w2a, b2a, w2b, b2b, w2c, b2c,
                                          (float*)d_out, n);
}

// round 4
// speedup vs baseline: 1.4234x; 1.4234x over previous
#include <cuda_runtime.h>
#include <cstdint>

#define T_HASH 524288      // 2^19 -> mod == & mask, low-32-bit arithmetic suffices
#define HMASK  (T_HASH - 1)
#define PI2    2654435761u
#define PI3    805459861u

// ---- packed f32x2 helpers (Blackwell FFMA2 is only reachable via PTX) ----
__device__ __forceinline__ unsigned long long pk2(float v) {
    unsigned long long r;
    asm("mov.b64 %0, {%1, %1};" : "=l"(r) : "f"(v));
    return r;
}
__device__ __forceinline__ unsigned long long fma2(unsigned long long a,
                                                   unsigned long long b,
                                                   unsigned long long c) {
    unsigned long long d;
    asm("fma.rn.f32x2 %0, %1, %2, %3;" : "=l"(d) : "l"(a), "l"(b), "l"(c));
    return d;
}
__device__ __forceinline__ void unpk(unsigned long long v, float& a, float& b) {
    asm("mov.b64 {%0, %1}, %2;" : "=f"(a), "=f"(b) : "l"(v));
}

// constant-memory weight layout (float offsets) — all reads are warp-uniform
// with compile-time indices -> LDC/LDCU on the uniform port, off the L1/smem pipe.
#define OW1A 0       // [32,64]  2048
#define OB1A 2048    // [64]
#define OW1B 2112    // [64,16]  1024
#define OB1B 3136    // [16]
#define OW2A 3152    // [43,64]  2752
#define OB2A 5904    // [64]
#define OW2B 5968    // [64,64]  4096
#define OB2B 10064   // [64]
#define OW2C 10128   // [64,3]   192
#define OB2C 10320   // [3]
#define SWTOT 10324  // 41.3 KB < 64 KB constant limit

__constant__ __align__(16) float cW[SWTOT];

__global__ __launch_bounds__(128, 2)
void ngp_fused_kernel(const float* __restrict__ x, const float* __restrict__ ddir,
                      const float* __restrict__ tables,
                      float* __restrict__ out, int n)
{
    int i = blockIdx.x * blockDim.x + threadIdx.x;
    if (i >= n) return;

    float x0 = x[3 * i + 0], x1 = x[3 * i + 1], x2 = x[3 * i + 2];
    float d0 = ddir[3 * i + 0], d1 = ddir[3 * i + 1], d2 = ddir[3 * i + 2];

    float xs0 = __fdiv_rn(x0, 3.0f), xs1 = __fdiv_rn(x1, 3.0f), xs2 = __fdiv_rn(x2, 3.0f);
    bool mask = (fabsf(xs0) < 0.5f) && (fabsf(xs1) < 0.5f) && (fabsf(xs2) < 0.5f);
    float xu0 = xs0 + 0.5f, xu1 = xs1 + 0.5f, xu2 = xs2 + 0.5f;

    // ---------------- hash-grid feature gather ----------------
    const float NLv[16] = {16.f, 22.f, 30.f, 42.f, 58.f, 80.f, 110.f, 152.f,
                           209.f, 288.f, 397.f, 547.f, 754.f, 1039.f, 1432.f, 1974.f};
    float feats[32];
    const float2* tb2 = (const float2*)tables;

    #pragma unroll
    for (int l = 0; l < 16; l++) {
        float nl = NLv[l];
        float p0 = xu0 * nl, p1 = xu1 * nl, p2 = xu2 * nl;
        float f0 = floorf(p0), f1 = floorf(p1), f2 = floorf(p2);
        float r0 = p0 - f0, r1 = p1 - f1, r2 = p2 - f2;
        float a0 = 1.0f - r0, a1 = 1.0f - r1, a2 = 1.0f - r2;

        // int64 hash ≡ low-32-bit hash because T = 2^19 and % T picks low bits
        unsigned hx0 = (unsigned)(int)f0;                 // * 1
        unsigned hy0 = (unsigned)(int)f1 * PI2;
        unsigned hz0 = (unsigned)(int)f2 * PI3;
        unsigned hx1 = hx0 + (r0 > 0.0f ? 1u   : 0u);     // ceil variant
        unsigned hy1 = hy0 + (r1 > 0.0f ? PI2  : 0u);
        unsigned hz1 = hz0 + (r2 > 0.0f ? PI3  : 0u);

        const float2* tbl = tb2 + (size_t)l * T_HASH;
        float acc0 = 0.0f, acc1 = 0.0f;
        // CEIL bit masks per vertex k: x:{1,5,6,7}=0xE2 y:{2,4,6,7}=0xD4 z:{3,4,5,7}=0xB8
        #pragma unroll
        for (int k = 0; k < 8; k++) {
            unsigned hh = (((0xE2 >> k) & 1) ? hx1 : hx0)
                        ^ (((0xD4 >> k) & 1) ? hy1 : hy0)
                        ^ (((0xB8 >> k) & 1) ? hz1 : hz0);
            hh &= HMASK;
            // WEIGHT bits (grid_sample mismatch, faithful): x=k&1, y=k&2, z=k&4
            float w = ((k & 1) ? r0 : a0) * ((k & 2) ? r1 : a1) * ((k & 4) ? r2 : a2);
            float2 t = __ldg(tbl + hh);
            acc0 = fmaf(w, t.x, acc0);
            acc1 = fmaf(w, t.y, acc1);
        }
        feats[2 * l + 0] = acc0;
        feats[2 * l + 1] = acc1;
    }

    // ---------------- MLP layer 1a: 32 -> 64, relu ----------------
    unsigned long long acc[32];
    {
        const unsigned long long* pb = (const unsigned long long*)(cW + OB1A);
        #pragma unroll
        for (int j = 0; j < 32; j++) acc[j] = pb[j];
        #pragma unroll 4
        for (int k = 0; k < 32; k++) {
            unsigned long long bv = pk2(feats[k]);
            const ulonglong2* wr = (const ulonglong2*)(cW + OW1A + k * 64);
            #pragma unroll
            for (int j = 0; j < 16; j++) {
                ulonglong2 ww = wr[j];
                acc[2 * j + 0] = fma2(bv, ww.x, acc[2 * j + 0]);
                acc[2 * j + 1] = fma2(bv, ww.y, acc[2 * j + 1]);
            }
        }
    }
    float h1[64];
    #pragma unroll
    for (int j = 0; j < 32; j++) {
        float a, b;
        unpk(acc[j], a, b);
        h1[2 * j + 0] = fmaxf(a, 0.0f);
        h1[2 * j + 1] = fmaxf(b, 0.0f);
    }

    // ---------------- MLP layer 1b: 64 -> 16 (no relu) ----------------
    float hh16[16];
    {
        unsigned long long acc2[8];
        const unsigned long long* pb = (const unsigned long long*)(cW + OB1B);
        #pragma unroll
        for (int j = 0; j < 8; j++) acc2[j] = pb[j];
        #pragma unroll 8
        for (int k = 0; k < 64; k++) {
            unsigned long long bv = pk2(h1[k]);
            const ulonglong2* wr = (const ulonglong2*)(cW + OW1B + k * 16);
            #pragma unroll
            for (int j = 0; j < 4; j++) {
                ulonglong2 ww = wr[j];
                acc2[2 * j + 0] = fma2(bv, ww.x, acc2[2 * j + 0]);
                acc2[2 * j + 1] = fma2(bv, ww.y, acc2[2 * j + 1]);
            }
        }
        #pragma unroll
        for (int j = 0; j < 8; j++) unpk(acc2[j], hh16[2 * j], hh16[2 * j + 1]);
    }

    float sigma = mask ? __expf(hh16[0]) : 0.0f;

    // ---------------- z = [h(16), d(3), sin/cos posenc(24)] ----------------
    float z[43];
    #pragma unroll
    for (int j = 0; j < 16; j++) z[j] = hh16[j];
    z[16] = d0; z[17] = d1; z[18] = d2;
    #pragma unroll
    for (int q = 0; q < 4; q++) {
        float m = (float)(1 << q);
        float s, c;
        __sincosf(m * d0, &s, &c); z[19 + 6 * q + 0] = s; z[22 + 6 * q + 0] = c;
        __sincosf(m * d1, &s, &c); z[19 + 6 * q + 1] = s; z[22 + 6 * q + 1] = c;
        __sincosf(m * d2, &s, &c); z[19 + 6 * q + 2] = s; z[22 + 6 * q + 2] = c;
    }

    // ---------------- MLP layer 2a: 43 -> 64, relu ----------------
    {
        const unsigned long long* pb = (const unsigned long long*)(cW + OB2A);
        #pragma unroll
        for (int j = 0; j < 32; j++) acc[j] = pb[j];
        #pragma unroll 4
        for (int k = 0; k < 43; k++) {
            unsigned long long bv = pk2(z[k]);
            const ulonglong2* wr = (const ulonglong2*)(cW + OW2A + k * 64);
            #pragma unroll
            for (int j = 0; j < 16; j++) {
                ulonglong2 ww = wr[j];
                acc[2 * j + 0] = fma2(bv, ww.x, acc[2 * j + 0]);
                acc[2 * j + 1] = fma2(bv, ww.y, acc[2 * j + 1]);
            }
        }
        #pragma unroll
        for (int j = 0; j < 32; j++) {
            float a, b;
            unpk(acc[j], a, b);
            h1[2 * j + 0] = fmaxf(a, 0.0f);   // reuse h1 as za[64]
            h1[2 * j + 1] = fmaxf(b, 0.0f);
        }
    }

    // ---------------- MLP layer 2b: 64 -> 64, relu ----------------
    float zb[64];
    {
        const unsigned long long* pb = (const unsigned long long*)(cW + OB2B);
        #pragma unroll
        for (int j = 0; j < 32; j++) acc[j] = pb[j];
        #pragma unroll 4
        for (int k = 0; k < 64; k++) {
            unsigned long long bv = pk2(h1[k]);
            const ulonglong2* wr = (const ulonglong2*)(cW + OW2B + k * 64);
            #pragma unroll
            for (int j = 0; j < 16; j++) {
                ulonglong2 ww = wr[j];
                acc[2 * j + 0] = fma2(bv, ww.x, acc[2 * j + 0]);
                acc[2 * j + 1] = fma2(bv, ww.y, acc[2 * j + 1]);
            }
        }
        #pragma unroll
        for (int j = 0; j < 32; j++) {
            float a, b;
            unpk(acc[j], a, b);
            zb[2 * j + 0] = fmaxf(a, 0.0f);
            zb[2 * j + 1] = fmaxf(b, 0.0f);
        }
    }

    // ---------------- MLP layer 2c: 64 -> 3, sigmoid ----------------
    float c0 = cW[OB2C + 0], c1 = cW[OB2C + 1], c2 = cW[OB2C + 2];
    #pragma unroll 8
    for (int k = 0; k < 64; k++) {
        float v = zb[k];
        c0 = fmaf(v, cW[OW2C + 3 * k + 0], c0);
        c1 = fmaf(v, cW[OW2C + 3 * k + 1], c1);
        c2 = fmaf(v, cW[OW2C + 3 * k + 2], c2);
    }
    c0 = 1.0f / (1.0f + __expf(-c0));
    c1 = 1.0f / (1.0f + __expf(-c1));
    c2 = 1.0f / (1.0f + __expf(-c2));

    out[3 * i + 0] = mask ? c0 : 0.0f;
    out[3 * i + 1] = mask ? c1 : 0.0f;
    out[3 * i + 2] = mask ? c2 : 0.0f;
    out[3 * n + i] = sigma;
}

extern "C" void kernel_launch(void* const* d_in, const int* in_sizes, int n_in,
                              void* d_out, int out_size) {
    const float* x      = (const float*)d_in[0];
    const float* dd     = (const float*)d_in[1];
    const float* tables = (const float*)d_in[2];

    // Stage all MLP weights into constant memory (D2D async copies — graph-capturable,
    // allocation-free). Offsets match the cW layout above.
    const int srcIdx[10] = {3, 4, 5, 6, 7, 8, 9, 10, 11, 12};
    const int offs[10]   = {OW1A, OB1A, OW1B, OB1B, OW2A, OB2A, OW2B, OB2B, OW2C, OB2C};
    const int lens[10]   = {2048, 64, 1024, 16, 2752, 64, 4096, 64, 192, 3};
    for (int s = 0; s < 10; s++) {
        cudaMemcpyToSymbolAsync(cW, d_in[srcIdx[s]], lens[s] * sizeof(float),
                                offs[s] * sizeof(float), cudaMemcpyDeviceToDevice);
    }

    int n = in_sizes[0] / 3;
    int threads = 128;
    int blocks = (n + threads - 1) / threads;
    ngp_fused_kernel<<<blocks, threads>>>(x, dd, tables, (float*)d_out, n);
}

// round 6
// speedup vs baseline: 1.5887x; 1.1161x over previous
#include <cuda_runtime.h>
#include <cstdint>

#define T_HASH 524288      // 2^19 -> mod == & mask, low-32-bit arithmetic suffices
#define HMASK  (T_HASH - 1)
#define PI2    2654435761u
#define PI3    805459861u

// ---- packed f32x2 helpers (Blackwell FFMA2 is only reachable via PTX) ----
__device__ __forceinline__ unsigned long long pk2(float v) {
    unsigned long long r;
    asm("mov.b64 %0, {%1, %1};" : "=l"(r) : "f"(v));
    return r;
}
__device__ __forceinline__ unsigned long long fma2(unsigned long long a,
                                                   unsigned long long b,
                                                   unsigned long long c) {
    unsigned long long d;
    asm("fma.rn.f32x2 %0, %1, %2, %3;" : "=l"(d) : "l"(a), "l"(b), "l"(c));
    return d;
}
__device__ __forceinline__ void unpk(unsigned long long v, float& a, float& b) {
    asm("mov.b64 {%0, %1}, %2;" : "=f"(a), "=f"(b) : "l"(v));
}

// constant-memory weight layout (float offsets) — warp-uniform compile-time
// indexed reads -> LDC/LDCU on the uniform port, off the L1/smem pipe.
#define OW1A 0       // [32,64]  2048
#define OB1A 2048    // [64]
#define OW1B 2112    // [64,16]  1024
#define OB1B 3136    // [16]
#define OW2A 3152    // [43,64]  2752
#define OB2A 5904    // [64]
#define OW2B 5968    // [64,64]  4096
#define OB2B 10064   // [64]
#define OW2C 10128   // [64,3]   192
#define OB2C 10320   // [3]
#define SWTOT 10324  // 41.3 KB < 64 KB constant limit

__constant__ __align__(16) float cW[SWTOT];

// Issue 8 vertex loads + interpolation weights for level l into buffer slot s.
#define ISSUE(l, s) do {                                                        \
    const float nl = NLv[l];                                                    \
    float p0 = xu0 * nl, p1 = xu1 * nl, p2 = xu2 * nl;                          \
    float ff0 = floorf(p0), ff1 = floorf(p1), ff2 = floorf(p2);                 \
    float r0 = p0 - ff0, r1 = p1 - ff1, r2 = p2 - ff2;                          \
    float a0 = 1.0f - r0, a1 = 1.0f - r1, a2 = 1.0f - r2;                       \
    unsigned hx0 = (unsigned)(int)ff0;                                          \
    unsigned hy0 = (unsigned)(int)ff1 * PI2;                                    \
    unsigned hz0 = (unsigned)(int)ff2 * PI3;                                    \
    unsigned hx1 = hx0 + (r0 > 0.0f ? 1u  : 0u);                                \
    unsigned hy1 = hy0 + (r1 > 0.0f ? PI2 : 0u);                                \
    unsigned hz1 = hz0 + (r2 > 0.0f ? PI3 : 0u);                                \
    const float2* tbl = tb2 + (size_t)(l) * T_HASH;                             \
    _Pragma("unroll")                                                           \
    for (int k = 0; k < 8; k++) {                                               \
        unsigned hh = (((0xE2 >> k) & 1) ? hx1 : hx0)                           \
                    ^ (((0xD4 >> k) & 1) ? hy1 : hy0)                           \
                    ^ (((0xB8 >> k) & 1) ? hz1 : hz0);                          \
        hh &= HMASK;                                                            \
        tb[s][k] = __ldg(tbl + hh);                                             \
        wb[s][k] = ((k & 1) ? r0 : a0) * ((k & 2) ? r1 : a1)                    \
                 * ((k & 4) ? r2 : a2);                                         \
    }                                                                           \
} while (0)

// Reduce buffer slot s into the level-l feature pair and apply the two
// corresponding rank-1 layer-1a updates (inputs 2l, 2l+1 -> all 64 outputs).
#define CONSUME(l, s) do {                                                      \
    float f0 = 0.0f, f1 = 0.0f;                                                 \
    _Pragma("unroll")                                                           \
    for (int k = 0; k < 8; k++) {                                               \
        f0 = fmaf(wb[s][k], tb[s][k].x, f0);                                    \
        f1 = fmaf(wb[s][k], tb[s][k].y, f1);                                    \
    }                                                                           \
    unsigned long long bv0 = pk2(f0), bv1 = pk2(f1);                            \
    const ulonglong2* wr0 = (const ulonglong2*)(cW + OW1A + (2 * (l)) * 64);    \
    const ulonglong2* wr1 = (const ulonglong2*)(cW + OW1A + (2 * (l) + 1) * 64);\
    _Pragma("unroll")                                                           \
    for (int j = 0; j < 16; j++) {                                              \
        ulonglong2 w0 = wr0[j];                                                 \
        acc[2 * j + 0] = fma2(bv0, w0.x, acc[2 * j + 0]);                       \
        acc[2 * j + 1] = fma2(bv0, w0.y, acc[2 * j + 1]);                       \
        ulonglong2 w1 = wr1[j];                                                 \
        acc[2 * j + 0] = fma2(bv1, w1.x, acc[2 * j + 0]);                       \
        acc[2 * j + 1] = fma2(bv1, w1.y, acc[2 * j + 1]);                       \
    }                                                                           \
} while (0)

__global__ __launch_bounds__(128, 2)
void ngp_fused_kernel(const float* __restrict__ x, const float* __restrict__ ddir,
                      const float* __restrict__ tables,
                      float* __restrict__ out, int n)
{
    int i = blockIdx.x * blockDim.x + threadIdx.x;
    if (i >= n) return;

    float x0 = x[3 * i + 0], x1 = x[3 * i + 1], x2 = x[3 * i + 2];
    float d0 = ddir[3 * i + 0], d1 = ddir[3 * i + 1], d2 = ddir[3 * i + 2];

    float xs0 = __fdiv_rn(x0, 3.0f), xs1 = __fdiv_rn(x1, 3.0f), xs2 = __fdiv_rn(x2, 3.0f);
    bool mask = (fabsf(xs0) < 0.5f) && (fabsf(xs1) < 0.5f) && (fabsf(xs2) < 0.5f);
    float xu0 = xs0 + 0.5f, xu1 = xs1 + 0.5f, xu2 = xs2 + 0.5f;

    const float NLv[16] = {16.f, 22.f, 30.f, 42.f, 58.f, 80.f, 110.f, 152.f,
                           209.f, 288.f, 397.f, 547.f, 754.f, 1039.f, 1432.f, 1974.f};
    const float2* tb2 = (const float2*)tables;

    // ---- pipelined hash gather fused with MLP layer 1a (32 -> 64) ----
    unsigned long long acc[32];
    {
        const unsigned long long* pb = (const unsigned long long*)(cW + OB1A);
        #pragma unroll
        for (int j = 0; j < 32; j++) acc[j] = pb[j];
    }

    float2 tb[2][8];
    float  wb[2][8];

    ISSUE(0, 0);
    ISSUE(1, 1);
    #pragma unroll
    for (int l = 0; l < 16; l++) {
        CONSUME(l, l & 1);
        if (l + 2 < 16) ISSUE(l + 2, l & 1);
    }

    float h1[64];
    #pragma unroll
    for (int j = 0; j < 32; j++) {
        float a, b;
        unpk(acc[j], a, b);
        h1[2 * j + 0] = fmaxf(a, 0.0f);
        h1[2 * j + 1] = fmaxf(b, 0.0f);
    }

    // ---------------- MLP layer 1b: 64 -> 16 (no relu) ----------------
    float hh16[16];
    {
        unsigned long long acc2[8];
        const unsigned long long* pb = (const unsigned long long*)(cW + OB1B);
        #pragma unroll
        for (int j = 0; j < 8; j++) acc2[j] = pb[j];
        #pragma unroll 8
        for (int k = 0; k < 64; k++) {
            unsigned long long bv = pk2(h1[k]);
            const ulonglong2* wr = (const ulonglong2*)(cW + OW1B + k * 16);
            #pragma unroll
            for (int j = 0; j < 4; j++) {
                ulonglong2 ww = wr[j];
                acc2[2 * j + 0] = fma2(bv, ww.x, acc2[2 * j + 0]);
                acc2[2 * j + 1] = fma2(bv, ww.y, acc2[2 * j + 1]);
            }
        }
        #pragma unroll
        for (int j = 0; j < 8; j++) unpk(acc2[j], hh16[2 * j], hh16[2 * j + 1]);
    }

    float sigma = mask ? __expf(hh16[0]) : 0.0f;

    // ---------------- z = [h(16), d(3), sin/cos posenc(24)] ----------------
    float z[43];
    #pragma unroll
    for (int j = 0; j < 16; j++) z[j] = hh16[j];
    z[16] = d0; z[17] = d1; z[18] = d2;
    #pragma unroll
    for (int q = 0; q < 4; q++) {
        float m = (float)(1 << q);
        float s, c;
        __sincosf(m * d0, &s, &c); z[19 + 6 * q + 0] = s; z[22 + 6 * q + 0] = c;
        __sincosf(m * d1, &s, &c); z[19 + 6 * q + 1] = s; z[22 + 6 * q + 1] = c;
        __sincosf(m * d2, &s, &c); z[19 + 6 * q + 2] = s; z[22 + 6 * q + 2] = c;
    }

    // ---------------- MLP layer 2a: 43 -> 64, relu ----------------
    {
        const unsigned long long* pb = (const unsigned long long*)(cW + OB2A);
        #pragma unroll
        for (int j = 0; j < 32; j++) acc[j] = pb[j];
        #pragma unroll 4
        for (int k = 0; k < 43; k++) {
            unsigned long long bv = pk2(z[k]);
            const ulonglong2* wr = (const ulonglong2*)(cW + OW2A + k * 64);
            #pragma unroll
            for (int j = 0; j < 16; j++) {
                ulonglong2 ww = wr[j];
                acc[2 * j + 0] = fma2(bv, ww.x, acc[2 * j + 0]);
                acc[2 * j + 1] = fma2(bv, ww.y, acc[2 * j + 1]);
            }
        }
        #pragma unroll
        for (int j = 0; j < 32; j++) {
            float a, b;
            unpk(acc[j], a, b);
            h1[2 * j + 0] = fmaxf(a, 0.0f);   // reuse h1 as za[64]
            h1[2 * j + 1] = fmaxf(b, 0.0f);
        }
    }

    // ---------------- MLP layer 2b: 64 -> 64, relu ----------------
    float zb[64];
    {
        const unsigned long long* pb = (const unsigned long long*)(cW + OB2B);
        #pragma unroll
        for (int j = 0; j < 32; j++) acc[j] = pb[j];
        #pragma unroll 4
        for (int k = 0; k < 64; k++) {
            unsigned long long bv = pk2(h1[k]);
            const ulonglong2* wr = (const ulonglong2*)(cW + OW2B + k * 64);
            #pragma unroll
            for (int j = 0; j < 16; j++) {
                ulonglong2 ww = wr[j];
                acc[2 * j + 0] = fma2(bv, ww.x, acc[2 * j + 0]);
                acc[2 * j + 1] = fma2(bv, ww.y, acc[2 * j + 1]);
            }
        }
        #pragma unroll
        for (int j = 0; j < 32; j++) {
            float a, b;
            unpk(acc[j], a, b);
            zb[2 * j + 0] = fmaxf(a, 0.0f);
            zb[2 * j + 1] = fmaxf(b, 0.0f);
        }
    }

    // ---------------- MLP layer 2c: 64 -> 3, sigmoid ----------------
    float c0 = cW[OB2C + 0], c1 = cW[OB2C + 1], c2 = cW[OB2C + 2];
    #pragma unroll 8
    for (int k = 0; k < 64; k++) {
        float v = zb[k];
        c0 = fmaf(v, cW[OW2C + 3 * k + 0], c0);
        c1 = fmaf(v, cW[OW2C + 3 * k + 1], c1);
        c2 = fmaf(v, cW[OW2C + 3 * k + 2], c2);
    }
    c0 = 1.0f / (1.0f + __expf(-c0));
    c1 = 1.0f / (1.0f + __expf(-c1));
    c2 = 1.0f / (1.0f + __expf(-c2));

    out[3 * i + 0] = mask ? c0 : 0.0f;
    out[3 * i + 1] = mask ? c1 : 0.0f;
    out[3 * i + 2] = mask ? c2 : 0.0f;
    out[3 * n + i] = sigma;
}

extern "C" void kernel_launch(void* const* d_in, const int* in_sizes, int n_in,
                              void* d_out, int out_size) {
    const float* x      = (const float*)d_in[0];
    const float* dd     = (const float*)d_in[1];
    const float* tables = (const float*)d_in[2];

    // Stage all MLP weights into constant memory (D2D async copies — graph-capturable,
    // allocation-free). Offsets match the cW layout above.
    const int srcIdx[10] = {3, 4, 5, 6, 7, 8, 9, 10, 11, 12};
    const int offs[10]   = {OW1A, OB1A, OW1B, OB1B, OW2A, OB2A, OW2B, OB2B, OW2C, OB2C};
    const int lens[10]   = {2048, 64, 1024, 16, 2752, 64, 4096, 64, 192, 3};
    for (int s = 0; s < 10; s++) {
        cudaMemcpyToSymbolAsync(cW, d_in[srcIdx[s]], lens[s] * sizeof(float),
                                offs[s] * sizeof(float), cudaMemcpyDeviceToDevice);
    }

    int n = in_sizes[0] / 3;
    int threads = 128;
    int blocks = (n + threads - 1) / threads;
    ngp_fused_kernel<<<blocks, threads>>>(x, dd, tables, (float*)d_out, n);
}